// round 3
// baseline (speedup 1.0000x reference)
#include <cuda_runtime.h>
#include <math.h>

#define EPSF 1e-8f

struct F3 { float x, y, z; };

__device__ __forceinline__ F3 f3sub(F3 a, F3 b) { return {a.x - b.x, a.y - b.y, a.z - b.z}; }
__device__ __forceinline__ F3 f3cross(F3 a, F3 b) {
    return {a.y * b.z - a.z * b.y,
            a.z * b.x - a.x * b.z,
            a.x * b.y - a.y * b.x};
}
__device__ __forceinline__ float f3dot(F3 a, F3 b) { return a.x * b.x + a.y * b.y + a.z * b.z; }

// Matches the reference:
//   n1n = n1 / (safe_norm(n1) + EPS);  n2n likewise
//   cos = clip(dot(n1n, n2n), -1, 1); angle = acos(cos)
//   sign = sign(dot(n1n, v3))   (sign(0) == 0, like jnp.sign)
__device__ __forceinline__ float dihedral(F3 p1, F3 p2, F3 p3, F3 p4) {
    F3 v1 = f3sub(p2, p1);
    F3 v2 = f3sub(p3, p2);
    F3 v3 = f3sub(p4, p3);
    F3 n1 = f3cross(v1, v2);
    F3 n2 = f3cross(v2, v3);
    float s1 = f3dot(n1, n1);
    float s2 = f3dot(n2, n2);
    float norm1 = (s1 > 0.0f) ? sqrtf(s1) : 0.0f;
    float norm2 = (s2 > 0.0f) ? sqrtf(s2) : 0.0f;
    float i1 = 1.0f / (norm1 + EPSF);
    float i2 = 1.0f / (norm2 + EPSF);
    F3 n1n = {n1.x * i1, n1.y * i1, n1.z * i1};
    F3 n2n = {n2.x * i2, n2.y * i2, n2.z * i2};
    float c = f3dot(n1n, n2n);
    c = fminf(1.0f, fmaxf(-1.0f, c));
    float ang = acosf(c);
    float sg = f3dot(n1n, v3);
    float sign = (sg > 0.0f) ? 1.0f : ((sg < 0.0f) ? -1.0f : 0.0f);
    return ang * sign;
}

static constexpr int Lc = 4096;   // sequence length (power of 2)
static constexpr int Dc = 64;     // output features
static constexpr int TPB = 256;

__global__ void __launch_bounds__(TPB)
dihedral_encoder_kernel(const float* __restrict__ coords,
                        const float* __restrict__ W,      // (64, 6) row-major
                        const float* __restrict__ bias,   // (64,)
                        float* __restrict__ out,          // (B*L, 64)
                        int total)                        // B*L
{
    // Shared: W transposed to (6, 64) so matvec reads are float4-friendly, plus bias.
    __shared__ float sW[6 * Dc];
    __shared__ float sB[Dc];
    int t = threadIdx.x;
    if (t < Dc) {
        sB[t] = bias[t];
        #pragma unroll
        for (int j = 0; j < 6; j++) sW[j * Dc + t] = W[t * 6 + j];
    }
    __syncthreads();

    int idx = blockIdx.x * TPB + t;
    if (idx >= total) return;
    int l = idx & (Lc - 1);

    // Row = 12 floats = 3 float4 (48B-aligned since 48 % 16 == 0).
    const float4* row = reinterpret_cast<const float4*>(coords) + (size_t)idx * 3;
    float4 ra = row[0];
    float4 rb = row[1];
    float4 rc = row[2];
    F3 N  = {ra.x, ra.y, ra.z};
    F3 CA = {ra.w, rb.x, rb.y};
    F3 C  = {rb.z, rb.w, rc.x};

    // C_prev: C of residue l-1, clamped at l==0 to C[0].
    F3 Cp;
    if (l > 0) {
        float4 pb = row[-2];
        float4 pc = row[-1];
        Cp = {pb.z, pb.w, pc.x};
    } else {
        Cp = C;
    }

    // N_next / omega p3,p4 with reference's concat boundary semantics.
    F3 Nn, P3, P4;
    if (l < Lc - 1) {
        float4 na = row[3];
        float4 nb = row[4];
        Nn = {na.x, na.y, na.z};
        P3 = Nn;                       // om_p3[l] = N[l+1]
        P4 = {na.w, nb.x, nb.y};       // om_p4[l] = CA[l+1]
    } else {
        Nn = N;                        // N_next[L-1] = N[L-1]
        P3 = CA;                       // om_p3[L-1] = CA[L-1]
        P4 = CA;                       // om_p4[L-1] = CA[L-1]  (degenerate -> omega = 0)
    }

    float phi = dihedral(Cp, N, CA, C);
    float psi = dihedral(N, CA, C, Nn);
    float omg = dihedral(CA, C, P3, P4);

    // encoded = [sin(phi), sin(psi), sin(omega), cos(phi), cos(psi), cos(omega)]
    float e[6];
    __sincosf(phi, &e[0], &e[3]);
    __sincosf(psi, &e[1], &e[4]);
    __sincosf(omg, &e[2], &e[5]);

    // out[idx, :] = encoded @ W^T + b, via float4 chunks (16 x STG.128).
    float4* o4 = reinterpret_cast<float4*>(out + (size_t)idx * Dc);
    const float4* w4 = reinterpret_cast<const float4*>(sW);   // w4[j*16 + d]
    const float4* b4 = reinterpret_cast<const float4*>(sB);
    #pragma unroll
    for (int d = 0; d < Dc / 4; d++) {
        float4 acc = b4[d];
        #pragma unroll
        for (int j = 0; j < 6; j++) {
            float4 w = w4[j * (Dc / 4) + d];
            acc.x = fmaf(e[j], w.x, acc.x);
            acc.y = fmaf(e[j], w.y, acc.y);
            acc.z = fmaf(e[j], w.z, acc.z);
            acc.w = fmaf(e[j], w.w, acc.w);
        }
        o4[d] = acc;
    }
}

extern "C" void kernel_launch(void* const* d_in, const int* in_sizes, int n_in,
                              void* d_out, int out_size) {
    const float* coords = (const float*)d_in[0];   // (B, L, 4, 3) f32
    const float* W      = (const float*)d_in[1];   // (64, 6) f32
    const float* bias   = (const float*)d_in[2];   // (64,) f32
    float* out          = (float*)d_out;           // (B, L, 64) f32

    int total = in_sizes[0] / 12;                  // B*L residues
    int grid = (total + TPB - 1) / TPB;
    dihedral_encoder_kernel<<<grid, TPB>>>(coords, W, bias, out, total);
}

// round 6
// speedup vs baseline: 1.0187x; 1.0187x over previous
#include <cuda_runtime.h>
#include <math.h>

#define EPSF 1e-8f
typedef unsigned long long u64;

struct F3 { float x, y, z; };

__device__ __forceinline__ F3 f3sub(F3 a, F3 b) { return {a.x - b.x, a.y - b.y, a.z - b.z}; }
__device__ __forceinline__ F3 f3cross(F3 a, F3 b) {
    return {a.y * b.z - a.z * b.y,
            a.z * b.x - a.x * b.z,
            a.x * b.y - a.y * b.x};
}
__device__ __forceinline__ float f3dot(F3 a, F3 b) { return a.x * b.x + a.y * b.y + a.z * b.z; }

// ---- packed f32x2 helpers (sm_103a FFMA2; ptxas never auto-fuses, PTX only) ----
__device__ __forceinline__ u64 pack2(float a, float b) {
    u64 r; asm("mov.b64 %0, {%1, %2};" : "=l"(r) : "f"(a), "f"(b)); return r;
}
__device__ __forceinline__ u64 ffma2(u64 a, u64 b, u64 c) {
    u64 d; asm("fma.rn.f32x2 %0, %1, %2, %3;" : "=l"(d) : "l"(a), "l"(b), "l"(c)); return d;
}

// Reference semantics, analytically simplified:
//   angle = acos(clip(dot(n1n,n2n)));  out_angle = angle * sign(dot(n1n, v3))
//   sin(out_angle) = sign * sqrt(1 - c^2)   (sign==0 -> 0)
//   cos(out_angle) = c                      (sign==0 -> cos(0) = 1)
// sign(dot(n1n,v3)) == sign(dot(n1,v3)) since the normalizer is strictly positive.
__device__ __forceinline__ void dihedral_sc(F3 p1, F3 p2, F3 p3, F3 p4,
                                            float& s_out, float& c_out) {
    F3 v1 = f3sub(p2, p1);
    F3 v2 = f3sub(p3, p2);
    F3 v3 = f3sub(p4, p3);
    F3 n1 = f3cross(v1, v2);
    F3 n2 = f3cross(v2, v3);
    float s1 = f3dot(n1, n1);
    float s2 = f3dot(n2, n2);
    float norm1 = (s1 > 0.0f) ? sqrtf(s1) : 0.0f;   // _safe_norm
    float norm2 = (s2 > 0.0f) ? sqrtf(s2) : 0.0f;
    float inv = __fdividef(1.0f, (norm1 + EPSF) * (norm2 + EPSF));
    float c = f3dot(n1, n2) * inv;
    c = fminf(1.0f, fmaxf(-1.0f, c));
    float sg = f3dot(n1, v3);
    float sinmag = sqrtf(fmaxf(fmaf(-c, c, 1.0f), 0.0f));
    s_out = (sg > 0.0f) ? sinmag : ((sg < 0.0f) ? -sinmag : 0.0f);
    c_out = (sg != 0.0f) ? c : 1.0f;
}

static constexpr int Lc  = 4096;   // sequence length (power of 2)
static constexpr int Dc  = 64;     // output features
static constexpr int TPB = 128;
static constexpr int RPT = 2;      // residues per thread

// Compute the 6-vector [sin phi, sin psi, sin omega, cos phi, cos psi, cos omega]
__device__ __forceinline__ void residue_encode(const float4* __restrict__ row, int l, float e[6]) {
    float4 ra = row[0];
    float4 rb = row[1];
    float4 rc = row[2];
    F3 N  = {ra.x, ra.y, ra.z};
    F3 CA = {ra.w, rb.x, rb.y};
    F3 C  = {rb.z, rb.w, rc.x};

    F3 Cp;
    if (l > 0) {
        float4 pb = row[-2];
        float4 pc = row[-1];
        Cp = {pb.z, pb.w, pc.x};
    } else {
        Cp = C;                                 // C_prev[0] = C[0]
    }

    F3 Nn, P3, P4;
    if (l < Lc - 1) {
        float4 na = row[3];
        float4 nb = row[4];
        Nn = {na.x, na.y, na.z};                // N_next[l] = N[l+1]
        P3 = Nn;                                // om_p3[l]  = N[l+1]
        P4 = {na.w, nb.x, nb.y};                // om_p4[l]  = CA[l+1]
    } else {
        Nn = N;                                 // N_next[L-1] = N[L-1]
        P3 = CA;                                // om_p3[L-1]  = CA[L-1]
        P4 = CA;                                // om_p4[L-1]  = CA[L-1] (degenerate)
    }

    dihedral_sc(Cp, N, CA, C,  e[0], e[3]);     // phi
    dihedral_sc(N, CA, C, Nn,  e[1], e[4]);     // psi
    dihedral_sc(CA, C, P3, P4, e[2], e[5]);     // omega
}

__global__ void __launch_bounds__(TPB)
dihedral_encoder_kernel(const float* __restrict__ coords,
                        const float* __restrict__ W,      // (64, 6) row-major
                        const float* __restrict__ bias,   // (64,)
                        float* __restrict__ out,          // (B*L, 64)
                        int total)
{
    __shared__ __align__(16) float sW[6 * Dc];  // transposed: sW[j*64 + d] = W[d][j]
    __shared__ __align__(16) float sB[Dc];
    int t = threadIdx.x;
    if (t < Dc) {
        sB[t] = bias[t];
        #pragma unroll
        for (int j = 0; j < 6; j++) sW[j * Dc + t] = W[t * 6 + j];
    }
    __syncthreads();

    int idx0 = blockIdx.x * (TPB * RPT) + t;
    int idx1 = idx0 + TPB;
    if (idx0 >= total) return;
    bool has1 = (idx1 < total);

    int l0 = idx0 & (Lc - 1);
    int l1 = idx1 & (Lc - 1);

    float e0[6], e1[6];
    residue_encode(reinterpret_cast<const float4*>(coords) + (size_t)idx0 * 3, l0, e0);
    if (has1)
        residue_encode(reinterpret_cast<const float4*>(coords) + (size_t)idx1 * 3, l1, e1);
    else {
        #pragma unroll
        for (int j = 0; j < 6; j++) e1[j] = 0.0f;
    }

    u64 e0p[6], e1p[6];
    #pragma unroll
    for (int j = 0; j < 6; j++) {
        e0p[j] = pack2(e0[j], e0[j]);
        e1p[j] = pack2(e1[j], e1[j]);
    }

    const ulonglong2* w2 = reinterpret_cast<const ulonglong2*>(sW);   // w2[j*16 + d]
    const ulonglong2* b2 = reinterpret_cast<const ulonglong2*>(sB);
    ulonglong2* o0 = reinterpret_cast<ulonglong2*>(out + (size_t)idx0 * Dc);
    ulonglong2* o1 = reinterpret_cast<ulonglong2*>(out + (size_t)idx1 * Dc);

    #pragma unroll
    for (int d = 0; d < Dc / 4; d++) {
        ulonglong2 bb = b2[d];
        u64 a0x = bb.x, a0y = bb.y;
        u64 a1x = bb.x, a1y = bb.y;
        #pragma unroll
        for (int j = 0; j < 6; j++) {
            ulonglong2 w = w2[j * (Dc / 4) + d];
            a0x = ffma2(e0p[j], w.x, a0x);
            a0y = ffma2(e0p[j], w.y, a0y);
            a1x = ffma2(e1p[j], w.x, a1x);
            a1y = ffma2(e1p[j], w.y, a1y);
        }
        ulonglong2 r0; r0.x = a0x; r0.y = a0y;
        o0[d] = r0;
        if (has1) {
            ulonglong2 r1; r1.x = a1x; r1.y = a1y;
            o1[d] = r1;
        }
    }
}

extern "C" void kernel_launch(void* const* d_in, const int* in_sizes, int n_in,
                              void* d_out, int out_size) {
    const float* coords = (const float*)d_in[0];   // (B, L, 4, 3) f32
    const float* W      = (const float*)d_in[1];   // (64, 6) f32
    const float* bias   = (const float*)d_in[2];   // (64,) f32
    float* out          = (float*)d_out;           // (B, L, 64) f32

    int total = in_sizes[0] / 12;                  // B*L residues
    int per_block = TPB * RPT;
    int grid = (total + per_block - 1) / per_block;
    dihedral_encoder_kernel<<<grid, TPB>>>(coords, W, bias, out, total);
}

// round 8
// speedup vs baseline: 1.2907x; 1.2670x over previous
#include <cuda_runtime.h>
#include <math.h>

#define EPSF 1e-8f

struct F3 { float x, y, z; };

__device__ __forceinline__ F3 f3sub(F3 a, F3 b) { return {a.x - b.x, a.y - b.y, a.z - b.z}; }
__device__ __forceinline__ F3 f3cross(F3 a, F3 b) {
    return {a.y * b.z - a.z * b.y,
            a.z * b.x - a.x * b.z,
            a.x * b.y - a.y * b.x};
}
__device__ __forceinline__ float f3dot(F3 a, F3 b) { return a.x * b.x + a.y * b.y + a.z * b.z; }

// Reference semantics, analytically simplified (validated rel_err 6e-6 in R3/R6):
//   sin(angle*sign) = sign * sqrt(1 - c^2),  cos(angle*sign) = c  (sign==0 -> (0,1))
//   sign(dot(n1n,v3)) == sign(dot(n1,v3)) since the normalizer is strictly positive.
__device__ __forceinline__ void dihedral_sc(F3 p1, F3 p2, F3 p3, F3 p4,
                                            float& s_out, float& c_out) {
    F3 v1 = f3sub(p2, p1);
    F3 v2 = f3sub(p3, p2);
    F3 v3 = f3sub(p4, p3);
    F3 n1 = f3cross(v1, v2);
    F3 n2 = f3cross(v2, v3);
    float s1 = f3dot(n1, n1);
    float s2 = f3dot(n2, n2);
    float norm1 = (s1 > 0.0f) ? sqrtf(s1) : 0.0f;   // _safe_norm
    float norm2 = (s2 > 0.0f) ? sqrtf(s2) : 0.0f;
    float inv = __fdividef(1.0f, (norm1 + EPSF) * (norm2 + EPSF));
    float c = f3dot(n1, n2) * inv;
    c = fminf(1.0f, fmaxf(-1.0f, c));
    float sg = f3dot(n1, v3);
    float sinmag = sqrtf(fmaxf(fmaf(-c, c, 1.0f), 0.0f));
    s_out = (sg > 0.0f) ? sinmag : ((sg < 0.0f) ? -sinmag : 0.0f);
    c_out = (sg != 0.0f) ? c : 1.0f;
}

static constexpr int Lc  = 4096;   // sequence length (power of 2, TPB divides it)
static constexpr int Dc  = 64;     // output features
static constexpr int TPB = 128;    // threads per block == residues per block

__global__ void __launch_bounds__(TPB)
dihedral_encoder_kernel(const float* __restrict__ coords,
                        const float* __restrict__ W,      // (64, 6) row-major
                        const float* __restrict__ bias,   // (64,)
                        float* __restrict__ out,          // (B*L, 64)
                        int total)
{
    __shared__ __align__(16) float sW[6 * Dc];   // transposed: sW[j*64 + d] = W[d][j]
    __shared__ __align__(16) float sB[Dc];
    __shared__ float sE[TPB * 8];                // per-residue encoded 6-vector (pad to 8)

    int t = threadIdx.x;
    if (t < Dc) {
        sB[t] = bias[t];
        #pragma unroll
        for (int j = 0; j < 6; j++) sW[j * Dc + t] = W[t * 6 + j];
    }

    // ---------------- Phase A: residue t -> encoded 6-vector in sE ----------------
    int g0 = blockIdx.x * TPB;       // first residue of this block
    int g  = g0 + t;
    bool valid = (g < total);
    if (valid) {
        int l = g & (Lc - 1);
        const float4* row = reinterpret_cast<const float4*>(coords) + (size_t)g * 3;
        float4 ra = row[0];
        float4 rb = row[1];
        float4 rc = row[2];
        F3 N  = {ra.x, ra.y, ra.z};
        F3 CA = {ra.w, rb.x, rb.y};
        F3 C  = {rb.z, rb.w, rc.x};

        F3 Cp;
        if (l > 0) {
            float4 pb = row[-2];
            float4 pc = row[-1];
            Cp = {pb.z, pb.w, pc.x};
        } else {
            Cp = C;                              // C_prev[0] = C[0]
        }

        F3 Nn, P3, P4;
        if (l < Lc - 1) {
            float4 na = row[3];
            float4 nb = row[4];
            Nn = {na.x, na.y, na.z};             // N_next[l] = N[l+1]
            P3 = Nn;                             // om_p3[l]  = N[l+1]
            P4 = {na.w, nb.x, nb.y};             // om_p4[l]  = CA[l+1]
        } else {
            Nn = N;                              // N_next[L-1] = N[L-1]
            P3 = CA;                             // om_p3[L-1]  = CA[L-1]
            P4 = CA;                             // om_p4[L-1]  = CA[L-1] (degenerate)
        }

        float e[6];
        dihedral_sc(Cp, N, CA, C,  e[0], e[3]);  // phi
        dihedral_sc(N, CA, C, Nn,  e[1], e[4]);  // psi
        dihedral_sc(CA, C, P3, P4, e[2], e[5]);  // omega

        #pragma unroll
        for (int j = 0; j < 6; j++) sE[t * 8 + j] = e[j];
    } else {
        #pragma unroll
        for (int j = 0; j < 6; j++) sE[t * 8 + j] = 0.0f;
    }
    __syncthreads();

    // ---------------- Phase B: coalesced matvec + store ----------------
    // Thread owns a FIXED 4-column chunk: chunk = t & 15, subrow = t >> 4.
    // Warp lanes cover 512 contiguous output bytes per store (4 lines/wavefronts,
    // vs 32 with row-per-thread stores).
    int chunk  = t & 15;
    int subrow = t >> 4;

    const float4* w4 = reinterpret_cast<const float4*>(sW);   // w4[j*16 + chunk]
    float4 wreg[6];
    #pragma unroll
    for (int j = 0; j < 6; j++) wreg[j] = w4[j * 16 + chunk];
    float4 breg = reinterpret_cast<const float4*>(sB)[chunk];

    float4* outBase = reinterpret_cast<float4*>(out + (size_t)g0 * Dc);

    #pragma unroll
    for (int it = 0; it < 16; it++) {
        int row = it * 8 + subrow;               // local residue 0..127
        if (g0 + row < total) {
            float4 acc = breg;
            #pragma unroll
            for (int j = 0; j < 6; j++) {
                float ej = sE[row * 8 + j];      // 2-address broadcast LDS per warp
                acc.x = fmaf(ej, wreg[j].x, acc.x);
                acc.y = fmaf(ej, wreg[j].y, acc.y);
                acc.z = fmaf(ej, wreg[j].z, acc.z);
                acc.w = fmaf(ej, wreg[j].w, acc.w);
            }
            outBase[row * 16 + chunk] = acc;     // fully coalesced across the warp
        }
    }
}

extern "C" void kernel_launch(void* const* d_in, const int* in_sizes, int n_in,
                              void* d_out, int out_size) {
    const float* coords = (const float*)d_in[0];   // (B, L, 4, 3) f32
    const float* W      = (const float*)d_in[1];   // (64, 6) f32
    const float* bias   = (const float*)d_in[2];   // (64,) f32
    float* out          = (float*)d_out;           // (B, L, 64) f32

    int total = in_sizes[0] / 12;                  // B*L residues
    int grid = (total + TPB - 1) / TPB;
    dihedral_encoder_kernel<<<grid, TPB>>>(coords, W, bias, out, total);
}

// round 10
// speedup vs baseline: 1.6055x; 1.2439x over previous
#include <cuda_runtime.h>
#include <math.h>

#define EPSF 1e-8f
typedef unsigned long long u64;

struct F3 { float x, y, z; };

__device__ __forceinline__ F3 f3sub(F3 a, F3 b) { return {a.x - b.x, a.y - b.y, a.z - b.z}; }
__device__ __forceinline__ F3 f3cross(F3 a, F3 b) {
    return {a.y * b.z - a.z * b.y,
            a.z * b.x - a.x * b.z,
            a.x * b.y - a.y * b.x};
}
__device__ __forceinline__ float f3dot(F3 a, F3 b) { return a.x * b.x + a.y * b.y + a.z * b.z; }

// ---- packed f32x2 helpers (sm_103a FFMA2; PTX-only, ptxas never auto-fuses) ----
__device__ __forceinline__ u64 pack2(float a, float b) {
    u64 r; asm("mov.b64 %0, {%1, %2};" : "=l"(r) : "f"(a), "f"(b)); return r;
}
__device__ __forceinline__ u64 ffma2(u64 a, u64 b, u64 c) {
    u64 d; asm("fma.rn.f32x2 %0, %1, %2, %3;" : "=l"(d) : "l"(a), "l"(b), "l"(c)); return d;
}

// Reference semantics, analytically simplified (validated rel_err ~6e-6 since R3):
//   sin(angle*sign) = sign * sqrt(1 - c^2),  cos(angle*sign) = c  (sign==0 -> (0,1))
//   sign(dot(n1n,v3)) == sign(dot(n1,v3)) since the normalizer is strictly positive.
__device__ __forceinline__ void dihedral_sc(F3 p1, F3 p2, F3 p3, F3 p4,
                                            float& s_out, float& c_out) {
    F3 v1 = f3sub(p2, p1);
    F3 v2 = f3sub(p3, p2);
    F3 v3 = f3sub(p4, p3);
    F3 n1 = f3cross(v1, v2);
    F3 n2 = f3cross(v2, v3);
    float s1 = f3dot(n1, n1);
    float s2 = f3dot(n2, n2);
    float norm1 = (s1 > 0.0f) ? sqrtf(s1) : 0.0f;   // _safe_norm
    float norm2 = (s2 > 0.0f) ? sqrtf(s2) : 0.0f;
    float inv = __fdividef(1.0f, (norm1 + EPSF) * (norm2 + EPSF));
    float c = f3dot(n1, n2) * inv;
    c = fminf(1.0f, fmaxf(-1.0f, c));
    float sg = f3dot(n1, v3);
    float sinmag = sqrtf(fmaxf(fmaf(-c, c, 1.0f), 0.0f));
    s_out = (sg > 0.0f) ? sinmag : ((sg < 0.0f) ? -sinmag : 0.0f);
    c_out = (sg != 0.0f) ? c : 1.0f;
}

static constexpr int Lc  = 4096;   // sequence length (power of 2)
static constexpr int Dc  = 64;     // output features
static constexpr int TPB = 256;    // threads per block == residues per block
static constexpr int ROWS_PER_SUB = TPB / 16;   // phase-B iterations per thread

__device__ __forceinline__ void residue_e(const float4* __restrict__ row, int l, float e[6]) {
    float4 ra = row[0];
    float4 rb = row[1];
    float4 rc = row[2];
    F3 N  = {ra.x, ra.y, ra.z};
    F3 CA = {ra.w, rb.x, rb.y};
    F3 C  = {rb.z, rb.w, rc.x};

    F3 Cp;
    if (l > 0) {
        float4 pb = row[-2];
        float4 pc = row[-1];
        Cp = {pb.z, pb.w, pc.x};
    } else {
        Cp = C;                                  // C_prev[0] = C[0]
    }

    F3 Nn, P3, P4;
    if (l < Lc - 1) {
        float4 na = row[3];
        float4 nb = row[4];
        Nn = {na.x, na.y, na.z};                 // N_next[l] = N[l+1]
        P3 = Nn;                                 // om_p3[l]  = N[l+1]
        P4 = {na.w, nb.x, nb.y};                 // om_p4[l]  = CA[l+1]
    } else {
        Nn = N;                                  // N_next[L-1] = N[L-1]
        P3 = CA;                                 // om_p3[L-1]  = CA[L-1]
        P4 = CA;                                 // om_p4[L-1]  = CA[L-1] (degenerate)
    }

    dihedral_sc(Cp, N, CA, C,  e[0], e[3]);      // phi
    dihedral_sc(N, CA, C, Nn,  e[1], e[4]);      // psi
    dihedral_sc(CA, C, P3, P4, e[2], e[5]);      // omega
}

__global__ void __launch_bounds__(TPB)
dihedral_encoder_kernel(const float* __restrict__ coords,
                        const float* __restrict__ W,      // (64, 6) row-major
                        const float* __restrict__ bias,   // (64,)
                        float* __restrict__ out,          // (B*L, 64)
                        int total)
{
    __shared__ __align__(16) float sW[6 * Dc];   // transposed: sW[j*64 + d] = W[d][j]
    __shared__ __align__(16) float sB[Dc];
    // Per-residue encoded vector, each e_j pre-duplicated as a (e_j, e_j) u64 pair.
    // Row = 8 u64 (64 B); data in first 6. Phase B reads 3x LDS.128 broadcast per row.
    __shared__ __align__(16) u64 sEd[TPB * 8];

    int t = threadIdx.x;
    if (t < Dc) {
        sB[t] = bias[t];
        #pragma unroll
        for (int j = 0; j < 6; j++) sW[j * Dc + t] = W[t * 6 + j];
    }

    int g0 = blockIdx.x * TPB;
    int g  = g0 + t;
    bool allin = (g0 + TPB) <= total;

    // ---------------- Phase A: residue t -> duplicated e-pairs in sEd ----------------
    {
        float e[6];
        if (allin || g < total) {
            residue_e(reinterpret_cast<const float4*>(coords) + (size_t)g * 3,
                      g & (Lc - 1), e);
        } else {
            #pragma unroll
            for (int j = 0; j < 6; j++) e[j] = 0.0f;
        }
        ulonglong2* rowp = reinterpret_cast<ulonglong2*>(&sEd[t * 8]);
        ulonglong2 q0; q0.x = pack2(e[0], e[0]); q0.y = pack2(e[1], e[1]);
        ulonglong2 q1; q1.x = pack2(e[2], e[2]); q1.y = pack2(e[3], e[3]);
        ulonglong2 q2; q2.x = pack2(e[4], e[4]); q2.y = pack2(e[5], e[5]);
        rowp[0] = q0; rowp[1] = q1; rowp[2] = q2;
    }
    __syncthreads();

    // ---------------- Phase B: coalesced packed matvec + store ----------------
    // Thread owns fixed 4-col chunk (chunk = t & 15); warp covers 512 contiguous
    // output bytes per store iteration.
    int chunk  = t & 15;
    int subrow = t >> 4;                          // 0..15

    const float4* w4 = reinterpret_cast<const float4*>(sW);
    u64 wp[6][2];
    #pragma unroll
    for (int j = 0; j < 6; j++) {
        float4 w = w4[j * 16 + chunk];
        wp[j][0] = pack2(w.x, w.y);
        wp[j][1] = pack2(w.z, w.w);
    }
    float4 bb = reinterpret_cast<const float4*>(sB)[chunk];
    u64 bp0 = pack2(bb.x, bb.y);
    u64 bp1 = pack2(bb.z, bb.w);

    ulonglong2* outBase = reinterpret_cast<ulonglong2*>(out + (size_t)g0 * Dc);
    const ulonglong2* e2 = reinterpret_cast<const ulonglong2*>(sEd);

    if (allin) {
        #pragma unroll
        for (int it = 0; it < ROWS_PER_SUB; it++) {
            int row = it * 16 + subrow;
            ulonglong2 q0 = e2[row * 4 + 0];      // (e0,e0),(e1,e1)
            ulonglong2 q1 = e2[row * 4 + 1];      // (e2,e2),(e3,e3)
            ulonglong2 q2 = e2[row * 4 + 2];      // (e4,e4),(e5,e5)
            u64 a0 = bp0, a1 = bp1;
            a0 = ffma2(q0.x, wp[0][0], a0);  a1 = ffma2(q0.x, wp[0][1], a1);
            a0 = ffma2(q0.y, wp[1][0], a0);  a1 = ffma2(q0.y, wp[1][1], a1);
            a0 = ffma2(q1.x, wp[2][0], a0);  a1 = ffma2(q1.x, wp[2][1], a1);
            a0 = ffma2(q1.y, wp[3][0], a0);  a1 = ffma2(q1.y, wp[3][1], a1);
            a0 = ffma2(q2.x, wp[4][0], a0);  a1 = ffma2(q2.x, wp[4][1], a1);
            a0 = ffma2(q2.y, wp[5][0], a0);  a1 = ffma2(q2.y, wp[5][1], a1);
            ulonglong2 r; r.x = a0; r.y = a1;
            outBase[row * 16 + chunk] = r;        // fully coalesced STG.128
        }
    } else {
        #pragma unroll
        for (int it = 0; it < ROWS_PER_SUB; it++) {
            int row = it * 16 + subrow;
            if (g0 + row < total) {
                ulonglong2 q0 = e2[row * 4 + 0];
                ulonglong2 q1 = e2[row * 4 + 1];
                ulonglong2 q2 = e2[row * 4 + 2];
                u64 a0 = bp0, a1 = bp1;
                a0 = ffma2(q0.x, wp[0][0], a0);  a1 = ffma2(q0.x, wp[0][1], a1);
                a0 = ffma2(q0.y, wp[1][0], a0);  a1 = ffma2(q0.y, wp[1][1], a1);
                a0 = ffma2(q1.x, wp[2][0], a0);  a1 = ffma2(q1.x, wp[2][1], a1);
                a0 = ffma2(q1.y, wp[3][0], a0);  a1 = ffma2(q1.y, wp[3][1], a1);
                a0 = ffma2(q2.x, wp[4][0], a0);  a1 = ffma2(q2.x, wp[4][1], a1);
                a0 = ffma2(q2.y, wp[5][0], a0);  a1 = ffma2(q2.y, wp[5][1], a1);
                ulonglong2 r; r.x = a0; r.y = a1;
                outBase[row * 16 + chunk] = r;
            }
        }
    }
}

extern "C" void kernel_launch(void* const* d_in, const int* in_sizes, int n_in,
                              void* d_out, int out_size) {
    const float* coords = (const float*)d_in[0];   // (B, L, 4, 3) f32
    const float* W      = (const float*)d_in[1];   // (64, 6) f32
    const float* bias   = (const float*)d_in[2];   // (64,) f32
    float* out          = (float*)d_out;           // (B, L, 64) f32

    int total = in_sizes[0] / 12;                  // B*L residues
    int grid = (total + TPB - 1) / TPB;
    dihedral_encoder_kernel<<<grid, TPB>>>(coords, W, bias, out, total);
}